// round 15
// baseline (speedup 1.0000x reference)
#include <cuda_runtime.h>
#include <cuda_fp16.h>
#include <math.h>
#include <stdint.h>

// Problem constants
#define BB 16
#define NN 243
#define JJ 17
#define CC 512
#define HH 8
#define MROWS (BB * NN * JJ)      // 66096
#define BNF   (BB * NN)           // 3888
#define KDIM  512

// Scratch (device globals: allocation-free per harness rules)
__device__ __half g_qkvh[(size_t)MROWS * 1536];
__device__ float g_y[(size_t)MROWS * CC];
__device__ __half g_xh[(size_t)MROWS * CC];
__device__ __half g_ah[(size_t)MROWS * CC];
__device__ __half g_w1h[1536 * 512];   // Wqkv^T fp16, [N][K]
__device__ __half g_w2h[512 * 512];    // Wproj^T fp16

// ---------------------------------------------------------------------------
// PTX helpers
// ---------------------------------------------------------------------------
__device__ __forceinline__ uint32_t smem_u32(const void* p) {
    uint32_t a;
    asm("{ .reg .u64 t; cvta.to.shared.u64 t, %1; cvt.u32.u64 %0, t; }"
        : "=r"(a) : "l"(p));
    return a;
}

#define CP_ASYNC16(dst, src, sz) \
    asm volatile("cp.async.cg.shared.global [%0], [%1], 16, %2;\n" \
                 :: "r"((uint32_t)(dst)), "l"(src), "r"(sz))
#define CP_COMMIT() asm volatile("cp.async.commit_group;\n" ::: "memory")
#define CP_WAIT0()  asm volatile("cp.async.wait_group 0;\n" ::: "memory")

#define LDSM4(r0, r1, r2, r3, a) \
    asm volatile("ldmatrix.sync.aligned.m8n8.x4.shared.b16 {%0,%1,%2,%3}, [%4];" \
                 : "=r"(r0), "=r"(r1), "=r"(r2), "=r"(r3) : "r"(a))

// fp16-accumulate HMMA (2x rate of fp32-acc): D(f16) = A*B + C(f16)
__device__ __forceinline__ void mma16816h(uint32_t* c, const uint32_t* a, const uint32_t* b) {
    asm volatile(
        "mma.sync.aligned.m16n8k16.row.col.f16.f16.f16.f16 "
        "{%0,%1}, {%2,%3,%4,%5}, {%6,%7}, {%0,%1};\n"
        : "+r"(c[0]), "+r"(c[1])
        : "r"(a[0]), "r"(a[1]), "r"(a[2]), "r"(a[3]), "r"(b[0]), "r"(b[1]));
}

// ---------------------------------------------------------------------------
// fp16 HMMA GEMM with fp16 accumulate + chunked fp32 promotion.
// C(MxN) = A(MxK) @ B^T(NxK) + bias; fp16 acc within each BK=64 tile,
// promoted to fp32 after each tile (partial sums stay small -> ~4e-4 rel).
// BM=128, BN=128, BK=64, 512 threads (16 warps 4x4), warp tile 32x32.
// 2-stage double buffer; ldmatrix from 144B-padded rows (conflict-free).
// Output: fp16 (Ch) if Ch != null, else fp32 (Cf) with optional resid.
// ---------------------------------------------------------------------------
#define ROWB 144                       // 128B of k-data + 16B pad
#define ST_A 0
#define ST_B (128 * ROWB)              // 18432
#define STAGE_BYTES (ST_B + 128 * ROWB)    // 36864
#define GEMM_SMEM (2 * STAGE_BYTES)        // 73728

__device__ __forceinline__ void load_tile(
    uint32_t stage,
    const __half* __restrict__ Ah, const __half* __restrict__ Bh,
    int bm, int bn, int M, int kt, int tid)
{
    const int k0 = kt * 64;
#pragma unroll
    for (int i = 0; i < 2; i++) {     // A: 128 rows x 8 16B-chunks (1024 ld)
        int q = i * 512 + tid;
        int row = q >> 3, c = q & 7;
        uint32_t dof = row * ROWB + c * 16;
        size_t ga = (size_t)(bm + row) * KDIM + k0 + c * 8;
        int p = ((bm + row) < M) ? 16 : 0;
        CP_ASYNC16(stage + ST_A + dof, Ah + ga, p);
    }
#pragma unroll
    for (int i = 0; i < 2; i++) {     // B: 128 rows x 8 16B-chunks
        int q = i * 512 + tid;
        int row = q >> 3, c = q & 7;
        uint32_t dof = row * ROWB + c * 16;
        size_t gb = (size_t)(bn + row) * KDIM + k0 + c * 8;
        CP_ASYNC16(stage + ST_B + dof, Bh + gb, 16);
    }
}

__global__ void __launch_bounds__(512, 1) gemm_mma(
    const __half* __restrict__ Ah, const __half* __restrict__ Bh,
    const float* __restrict__ bias, const float* __restrict__ resid,
    float* __restrict__ Cf, __half* __restrict__ Ch, int M, int N)
{
    extern __shared__ char smem[];
    const uint32_t sb = smem_u32(smem);
    const int tid = threadIdx.x;
    const int w = tid >> 5, lane = tid & 31;
    const int wm = w & 3;                 // 4 warp-rows of 32
    const int wn = w >> 2;                // 4 warp-cols of 32
    const int bn = blockIdx.x << 7;       // BN=128
    const int bm = blockIdx.y << 7;       // BM=128

    float acc32[2][4][4];
    uint32_t acc16[2][4][2];
#pragma unroll
    for (int i = 0; i < 2; i++)
#pragma unroll
        for (int j = 0; j < 4; j++) {
#pragma unroll
            for (int e = 0; e < 4; e++) acc32[i][j][e] = 0.f;
            acc16[i][j][0] = 0u;
            acc16[i][j][1] = 0u;
        }

    const int lrow = lane & 15;
    const int lkb = (lane >> 4) << 4;     // k8-half byte offset within k16 chunk
    const uint32_t a_lane_off = (wm * 32 + lrow) * ROWB + lkb;
    const uint32_t b_lane_off = (wn * 32 + lrow) * ROWB + lkb;

    const int T = KDIM / 64;              // 8
    load_tile(sb, Ah, Bh, bm, bn, M, 0, tid);
    CP_COMMIT();

    for (int kt = 0; kt < T; kt++) {
        CP_WAIT0();                        // tile kt resident
        __syncthreads();                   // all warps done with other buffer

        if (kt + 1 < T) {
            load_tile(sb + ((kt + 1) & 1) * STAGE_BYTES, Ah, Bh, bm, bn, M, kt + 1, tid);
            CP_COMMIT();
        }

        const uint32_t stage = sb + (kt & 1) * STAGE_BYTES;
#pragma unroll
        for (int kc = 0; kc < 4; kc++) {   // 4 k16-chunks per BK=64
            const uint32_t kbo = kc * 32;  // 16 fp16 = 32B per k16-chunk
            uint32_t ah[2][4], bh[4][2];
#pragma unroll
            for (int mi = 0; mi < 2; mi++) {
                uint32_t ad = stage + a_lane_off + mi * (16 * ROWB) + kbo;
                LDSM4(ah[mi][0], ah[mi][1], ah[mi][2], ah[mi][3], ad + ST_A);
            }
#pragma unroll
            for (int nj = 0; nj < 2; nj++) {      // 2 n16 tiles
                uint32_t bd = stage + b_lane_off + nj * (16 * ROWB) + kbo;
                uint32_t h0, h1, h2r, h3;
                LDSM4(h0, h1, h2r, h3, bd + ST_B);
                bh[nj * 2 + 0][0] = h0; bh[nj * 2 + 0][1] = h2r;
                bh[nj * 2 + 1][0] = h1; bh[nj * 2 + 1][1] = h3;
            }
#pragma unroll
            for (int mi = 0; mi < 2; mi++)
#pragma unroll
                for (int nq = 0; nq < 4; nq++)
                    mma16816h(acc16[mi][nq], ah[mi], bh[nq]);
        }

        // promote fp16 partials (K=64 worth) into fp32 accumulators
#pragma unroll
        for (int mi = 0; mi < 2; mi++)
#pragma unroll
            for (int nq = 0; nq < 4; nq++) {
                float2 lo = __half22float2(*(const __half2*)&acc16[mi][nq][0]);
                float2 hi = __half22float2(*(const __half2*)&acc16[mi][nq][1]);
                acc32[mi][nq][0] += lo.x;
                acc32[mi][nq][1] += lo.y;
                acc32[mi][nq][2] += hi.x;
                acc32[mi][nq][3] += hi.y;
                acc16[mi][nq][0] = 0u;
                acc16[mi][nq][1] = 0u;
            }
    }

    // Epilogue: thread g*4+t holds (m=g, n=2t) and (m=g+8, n=2t) per 16x8 tile
    const int g = lane >> 2, t = lane & 3;
#pragma unroll
    for (int mi = 0; mi < 2; mi++) {
#pragma unroll
        for (int ni = 0; ni < 4; ni++) {
            int col = bn + wn * 32 + ni * 8 + t * 2;
            float bb0 = bias[col], bb1 = bias[col + 1];
            int r0 = bm + wm * 32 + mi * 16 + g;
            int r1 = r0 + 8;
            if (Ch) {                     // fp16 output
                if (r0 < M)
                    *(__half2*)(Ch + (size_t)r0 * N + col) =
                        __halves2half2(__float2half(acc32[mi][ni][0] + bb0),
                                       __float2half(acc32[mi][ni][1] + bb1));
                if (r1 < M)
                    *(__half2*)(Ch + (size_t)r1 * N + col) =
                        __halves2half2(__float2half(acc32[mi][ni][2] + bb0),
                                       __float2half(acc32[mi][ni][3] + bb1));
            } else {                      // fp32 output (+resid)
                if (r0 < M) {
                    float2 o;
                    o.x = acc32[mi][ni][0] + bb0;
                    o.y = acc32[mi][ni][1] + bb1;
                    if (resid) {
                        const float2 rr = *(const float2*)(resid + (size_t)r0 * N + col);
                        o.x += rr.x; o.y += rr.y;
                    }
                    *(float2*)(Cf + (size_t)r0 * N + col) = o;
                }
                if (r1 < M) {
                    float2 o;
                    o.x = acc32[mi][ni][2] + bb0;
                    o.y = acc32[mi][ni][3] + bb1;
                    if (resid) {
                        const float2 rr = *(const float2*)(resid + (size_t)r1 * N + col);
                        o.x += rr.x; o.y += rr.y;
                    }
                    *(float2*)(Cf + (size_t)r1 * N + col) = o;
                }
            }
        }
    }
}

// ---------------------------------------------------------------------------
// Elementwise fp32 -> fp16 convert
// ---------------------------------------------------------------------------
__global__ void cvt_kernel(const float* __restrict__ src,
                           __half* __restrict__ dst, int n4) {
    int i = blockIdx.x * blockDim.x + threadIdx.x;
    if (i >= n4) return;
    float4 v = ((const float4*)src)[i];
    __half2* dp = (__half2*)dst;
    dp[2 * i]     = __halves2half2(__float2half(v.x), __float2half(v.y));
    dp[2 * i + 1] = __halves2half2(__float2half(v.z), __float2half(v.w));
}

// Transpose to fp16: W (KxN row-major) -> hiT (NxK row-major)
__global__ void wsplit_kernel(const float* __restrict__ W,
                              __half* __restrict__ hiT, int K, int N) {
    __shared__ float t[32][33];
    const int n0 = blockIdx.x * 32, k0 = blockIdx.y * 32;
    const int tx = threadIdx.x, ty = threadIdx.y;
    for (int r = ty; r < 32; r += 8)
        t[r][tx] = W[(size_t)(k0 + r) * N + n0 + tx];
    __syncthreads();
    for (int r = ty; r < 32; r += 8) {
        float v = t[tx][r];                       // (k0+tx, n0+r)
        hiT[(size_t)(n0 + r) * K + k0 + tx] = __float2half(v);
    }
}

// ---------------------------------------------------------------------------
// Attention (R12/R14 proven version): 2 heads per 128-thread block; qkv fp16
// in, fp32 math, fp16 out. 3x3 register-tiled scores; padded rows; reg P@V.
// ---------------------------------------------------------------------------
#define APAD 68
__global__ __launch_bounds__(128)
void attn_kernel(const __half* __restrict__ qkv, __half* __restrict__ oh) {
    const int blk = blockIdx.x;           // 0 .. BNF*4-1
    const int bn = blk >> 2;
    const int h  = ((blk & 3) << 1) + (threadIdx.x >> 6);
    const int sl = threadIdx.x >> 6;      // slice 0/1
    const int d  = threadIdx.x & 63;

    __shared__ float qs[2][18][APAD];
    __shared__ float ks[2][18][APAD];
    __shared__ float vs[2][17][APAD];
    __shared__ float S[2][17][20];        // 80B rows (float4-aligned)

    const __half* base = qkv + (size_t)bn * 17 * 1536 + h * 64;
#pragma unroll
    for (int j = 0; j < 17; j++) {
        const __half* r = base + (size_t)j * 1536;
        qs[sl][j][d] = __half2float(r[d]);
        ks[sl][j][d] = __half2float(r[512 + d]);
        vs[sl][j][d] = __half2float(r[1024 + d]);
    }
    qs[sl][17][d] = 0.f;                  // zero pad row
    ks[sl][17][d] = 0.f;
    __syncthreads();

    // Scores: 6x6 grid of 3x3 tiles over the padded 18x18 domain; threads 0..35
    if (d < 36) {
        const int i0 = (d / 6) * 3;
        const int j0 = (d % 6) * 3;
        float a[3][3];
#pragma unroll
        for (int r = 0; r < 3; r++)
#pragma unroll
            for (int s = 0; s < 3; s++) a[r][s] = 0.f;

#pragma unroll
        for (int c = 0; c < 8; c++) {     // 8 chunks of 8 along head dim
            float qv[3][8], kv[3][8];
#pragma unroll
            for (int r = 0; r < 3; r++) {
                *(float4*)&qv[r][0] = *(const float4*)&qs[sl][i0 + r][c * 8];
                *(float4*)&qv[r][4] = *(const float4*)&qs[sl][i0 + r][c * 8 + 4];
                *(float4*)&kv[r][0] = *(const float4*)&ks[sl][j0 + r][c * 8];
                *(float4*)&kv[r][4] = *(const float4*)&ks[sl][j0 + r][c * 8 + 4];
            }
#pragma unroll
            for (int r = 0; r < 3; r++)
#pragma unroll
                for (int s = 0; s < 3; s++)
#pragma unroll
                    for (int e = 0; e < 8; e++)
                        a[r][s] += qv[r][e] * kv[s][e];
        }
#pragma unroll
        for (int r = 0; r < 3; r++)
#pragma unroll
            for (int s = 0; s < 3; s++)
                if (i0 + r < 17 && j0 + s < 17)
                    S[sl][i0 + r][j0 + s] = a[r][s] * 0.125f;
    }
    __syncthreads();

    if (d < 17) {
        float mx = -1e30f;
#pragma unroll
        for (int j = 0; j < 17; j++) mx = fmaxf(mx, S[sl][d][j]);
        float sum = 0.f;
#pragma unroll
        for (int j = 0; j < 17; j++) {
            float e = expf(S[sl][d][j] - mx);
            S[sl][d][j] = e;
            sum += e;
        }
        float inv = 1.f / sum;
#pragma unroll
        for (int j = 0; j < 17; j++) S[sl][d][j] *= inv;
    }
    __syncthreads();

    if (d == 0) {
        const int trip[13][3] = {
            {0,1,2},{1,2,3},{0,4,5},{4,5,6},{0,7,8},{7,8,9},{8,9,10},
            {7,8,11},{8,11,12},{11,12,13},{7,8,14},{8,14,15},{14,15,16}};
#pragma unroll
        for (int tt = 0; tt < 13; tt++) {
            int jp = trip[tt][0], j = trip[tt][1], jc = trip[tt][2];
            float half = S[sl][j][jp] * 0.5f;
            S[sl][j][jc] += half;
            S[sl][jc][j] += half;
        }
    }
    __syncthreads();

    // P@V: v cached in registers; S rows via float4 broadcast
    float v[17];
#pragma unroll
    for (int j = 0; j < 17; j++) v[j] = vs[sl][j][d];
#pragma unroll
    for (int i = 0; i < 17; i++) {
        const float4 s0 = *(const float4*)&S[sl][i][0];
        const float4 s1 = *(const float4*)&S[sl][i][4];
        const float4 s2 = *(const float4*)&S[sl][i][8];
        const float4 s3 = *(const float4*)&S[sl][i][12];
        const float s16 = S[sl][i][16];
        float o = s0.x * v[0] + s0.y * v[1] + s0.z * v[2] + s0.w * v[3]
                + s1.x * v[4] + s1.y * v[5] + s1.z * v[6] + s1.w * v[7]
                + s2.x * v[8] + s2.y * v[9] + s2.z * v[10] + s2.w * v[11]
                + s3.x * v[12] + s3.y * v[13] + s3.z * v[14] + s3.w * v[15]
                + s16 * v[16];
        oh[((size_t)(bn * 17 + i)) * 512 + h * 64 + d] = __float2half(o);
    }
}

// ---------------------------------------------------------------------------
// LayerNorm (no affine) over last dim 512
// ---------------------------------------------------------------------------
__global__ __launch_bounds__(128)
void ln_kernel(const float* __restrict__ Y, float* __restrict__ O) {
    const int row = blockIdx.x;
    const int t = threadIdx.x;
    const float4* yp = reinterpret_cast<const float4*>(Y + (size_t)row * 512);
    float4* op = reinterpret_cast<float4*>(O + (size_t)row * 512);

    float4 v = yp[t];
    float s = v.x + v.y + v.z + v.w;
    float q = v.x * v.x + v.y * v.y + v.z * v.z + v.w * v.w;
#pragma unroll
    for (int o = 16; o > 0; o >>= 1) {
        s += __shfl_xor_sync(0xffffffffu, s, o);
        q += __shfl_xor_sync(0xffffffffu, q, o);
    }
    __shared__ float ss[4], sq[4];
    int w = t >> 5;
    if ((t & 31) == 0) { ss[w] = s; sq[w] = q; }
    __syncthreads();
    s = ss[0] + ss[1] + ss[2] + ss[3];
    q = sq[0] + sq[1] + sq[2] + sq[3];

    const float inv512 = 1.f / 512.f;
    float mean = s * inv512;
    float var = q * inv512 - mean * mean;
    float r = rsqrtf(var + 1e-5f);

    float4 o4;
    o4.x = (v.x - mean) * r;
    o4.y = (v.y - mean) * r;
    o4.z = (v.z - mean) * r;
    o4.w = (v.w - mean) * r;
    op[t] = o4;
}

// ---------------------------------------------------------------------------
extern "C" void kernel_launch(void* const* d_in, const int* in_sizes, int n_in,
                              void* d_out, int out_size) {
    const float* x     = (const float*)d_in[0];
    const float* Wqkv  = (const float*)d_in[1];
    const float* bqkv  = (const float*)d_in[2];
    const float* Wproj = (const float*)d_in[3];
    const float* bproj = (const float*)d_in[4];
    float* out = (float*)d_out;

    float *y;
    __half *qkvh, *xh, *ah, *w1h, *w2h;
    cudaGetSymbolAddress((void**)&qkvh, g_qkvh);
    cudaGetSymbolAddress((void**)&y, g_y);
    cudaGetSymbolAddress((void**)&xh, g_xh);
    cudaGetSymbolAddress((void**)&ah, g_ah);
    cudaGetSymbolAddress((void**)&w1h, g_w1h);
    cudaGetSymbolAddress((void**)&w2h, g_w2h);

    cudaFuncSetAttribute(gemm_mma, cudaFuncAttributeMaxDynamicSharedMemorySize, GEMM_SMEM);

    // 1) converts
    const int n4 = MROWS * CC / 4;
    cvt_kernel<<<(n4 + 255) / 256, 256>>>(x, xh, n4);
    wsplit_kernel<<<dim3(1536 / 32, 512 / 32), dim3(32, 8)>>>(Wqkv, w1h, 512, 1536);
    wsplit_kernel<<<dim3(512 / 32, 512 / 32), dim3(32, 8)>>>(Wproj, w2h, 512, 512);

    // 2) GEMM1: qkv = x @ Wqkv + bqkv (fp16 out)
    gemm_mma<<<dim3(1536 / 128, (MROWS + 127) / 128), 512, GEMM_SMEM>>>(
        xh, w1h, bqkv, nullptr, nullptr, qkvh, MROWS, 1536);

    // 3) attention (fp16 in/out)
    attn_kernel<<<BNF * 4, 128>>>(qkvh, ah);

    // 4) GEMM2: y = att @ Wproj + bproj + x (fp32 out + resid)
    gemm_mma<<<dim3(512 / 128, (MROWS + 127) / 128), 512, GEMM_SMEM>>>(
        ah, w2h, bproj, x, y, nullptr, MROWS, 512);

    // 5) LayerNorm
    ln_kernel<<<MROWS, 128>>>(y, out);
}

// round 16
// speedup vs baseline: 1.1815x; 1.1815x over previous
#include <cuda_runtime.h>
#include <cuda_fp16.h>
#include <math.h>
#include <stdint.h>

// Problem constants
#define BB 16
#define NN 243
#define JJ 17
#define CC 512
#define HH 8
#define MROWS (BB * NN * JJ)      // 66096
#define BNF   (BB * NN)           // 3888
#define KDIM  512

// Scratch (device globals: allocation-free per harness rules)
__device__ __half g_qkvh[(size_t)MROWS * 1536];
__device__ __half g_xh[(size_t)MROWS * CC];
__device__ __half g_ah[(size_t)MROWS * CC];
__device__ __half g_w1h[1536 * 512];   // Wqkv^T fp16, [N][K]
__device__ __half g_w2h[512 * 512];    // Wproj^T fp16

// ---------------------------------------------------------------------------
// PTX helpers
// ---------------------------------------------------------------------------
__device__ __forceinline__ uint32_t smem_u32(const void* p) {
    uint32_t a;
    asm("{ .reg .u64 t; cvta.to.shared.u64 t, %1; cvt.u32.u64 %0, t; }"
        : "=r"(a) : "l"(p));
    return a;
}

#define CP_ASYNC16(dst, src, sz) \
    asm volatile("cp.async.cg.shared.global [%0], [%1], 16, %2;\n" \
                 :: "r"((uint32_t)(dst)), "l"(src), "r"(sz))
#define CP_COMMIT() asm volatile("cp.async.commit_group;\n" ::: "memory")
#define CP_WAIT0()  asm volatile("cp.async.wait_group 0;\n" ::: "memory")

#define LDSM4(r0, r1, r2, r3, a) \
    asm volatile("ldmatrix.sync.aligned.m8n8.x4.shared.b16 {%0,%1,%2,%3}, [%4];" \
                 : "=r"(r0), "=r"(r1), "=r"(r2), "=r"(r3) : "r"(a))

__device__ __forceinline__ void mma16816(float* c, const uint32_t* a, const uint32_t* b) {
    asm volatile(
        "mma.sync.aligned.m16n8k16.row.col.f32.f16.f16.f32 "
        "{%0,%1,%2,%3}, {%4,%5,%6,%7}, {%8,%9}, {%0,%1,%2,%3};\n"
        : "+f"(c[0]), "+f"(c[1]), "+f"(c[2]), "+f"(c[3])
        : "r"(a[0]), "r"(a[1]), "r"(a[2]), "r"(a[3]), "r"(b[0]), "r"(b[1]));
}

// ---------------------------------------------------------------------------
// GEMM1 (R14 proven config): C(MxN) = A(MxK) @ B^T(NxK) + bias, fp32 acc,
// fp16 output. BM=128, BN=128, BK=64, 256 threads (8 warps 2x4), warp 64x32.
// 2 CTAs/SM; 2-stage double buffer; 144B-padded rows (conflict-free ldmatrix).
// ---------------------------------------------------------------------------
#define ROWB 144
#define ST_A 0
#define ST_B (128 * ROWB)              // 18432
#define STAGE_BYTES (ST_B + 128 * ROWB)    // 36864
#define GEMM_SMEM (2 * STAGE_BYTES)        // 73728

__device__ __forceinline__ void load_tile(
    uint32_t stage,
    const __half* __restrict__ Ah, const __half* __restrict__ Bh,
    int bm, int bn, int M, int kt, int tid)
{
    const int k0 = kt * 64;
#pragma unroll
    for (int i = 0; i < 4; i++) {     // A: 128 rows x 8 16B-chunks
        int q = i * 256 + tid;
        int row = q >> 3, c = q & 7;
        uint32_t dof = row * ROWB + c * 16;
        size_t ga = (size_t)(bm + row) * KDIM + k0 + c * 8;
        int p = ((bm + row) < M) ? 16 : 0;
        CP_ASYNC16(stage + ST_A + dof, Ah + ga, p);
    }
#pragma unroll
    for (int i = 0; i < 4; i++) {     // B: 128 rows x 8 16B-chunks
        int q = i * 256 + tid;
        int row = q >> 3, c = q & 7;
        uint32_t dof = row * ROWB + c * 16;
        size_t gb = (size_t)(bn + row) * KDIM + k0 + c * 8;
        CP_ASYNC16(stage + ST_B + dof, Bh + gb, 16);
    }
}

__global__ void __launch_bounds__(256, 2) gemm_mma(
    const __half* __restrict__ Ah, const __half* __restrict__ Bh,
    const float* __restrict__ bias, __half* __restrict__ Ch, int M, int N)
{
    extern __shared__ char smem[];
    const uint32_t sb = smem_u32(smem);
    const int tid = threadIdx.x;
    const int w = tid >> 5, lane = tid & 31;
    const int wm = w & 1;
    const int wn = w >> 1;
    const int bn = blockIdx.x << 7;
    const int bm = blockIdx.y << 7;

    float acc[4][4][4];
#pragma unroll
    for (int i = 0; i < 4; i++)
#pragma unroll
        for (int j = 0; j < 4; j++)
#pragma unroll
            for (int e = 0; e < 4; e++) acc[i][j][e] = 0.f;

    const int lrow = lane & 15;
    const int lkb = (lane >> 4) << 4;
    const uint32_t a_lane_off = (wm * 64 + lrow) * ROWB + lkb;
    const uint32_t b_lane_off = (wn * 32 + lrow) * ROWB + lkb;

    const int T = KDIM / 64;              // 8
    load_tile(sb, Ah, Bh, bm, bn, M, 0, tid);
    CP_COMMIT();

    for (int kt = 0; kt < T; kt++) {
        CP_WAIT0();
        __syncthreads();

        if (kt + 1 < T) {
            load_tile(sb + ((kt + 1) & 1) * STAGE_BYTES, Ah, Bh, bm, bn, M, kt + 1, tid);
            CP_COMMIT();
        }

        const uint32_t stage = sb + (kt & 1) * STAGE_BYTES;
#pragma unroll
        for (int kc = 0; kc < 4; kc++) {
            const uint32_t kbo = kc * 32;
            uint32_t ah[4][4], bh[4][2];
#pragma unroll
            for (int mi = 0; mi < 4; mi++) {
                uint32_t ad = stage + a_lane_off + mi * (16 * ROWB) + kbo;
                LDSM4(ah[mi][0], ah[mi][1], ah[mi][2], ah[mi][3], ad + ST_A);
            }
#pragma unroll
            for (int nj = 0; nj < 2; nj++) {
                uint32_t bd = stage + b_lane_off + nj * (16 * ROWB) + kbo;
                uint32_t h0, h1, h2r, h3;
                LDSM4(h0, h1, h2r, h3, bd + ST_B);
                bh[nj * 2 + 0][0] = h0; bh[nj * 2 + 0][1] = h2r;
                bh[nj * 2 + 1][0] = h1; bh[nj * 2 + 1][1] = h3;
            }
#pragma unroll
            for (int mi = 0; mi < 4; mi++)
#pragma unroll
                for (int nq = 0; nq < 4; nq++)
                    mma16816(acc[mi][nq], ah[mi], bh[nq]);
        }
    }

    const int g = lane >> 2, t = lane & 3;
#pragma unroll
    for (int mi = 0; mi < 4; mi++) {
#pragma unroll
        for (int ni = 0; ni < 4; ni++) {
            int col = bn + wn * 32 + ni * 8 + t * 2;
            float bb0 = bias[col], bb1 = bias[col + 1];
            int r0 = bm + wm * 64 + mi * 16 + g;
            int r1 = r0 + 8;
            if (r0 < M)
                *(__half2*)(Ch + (size_t)r0 * N + col) =
                    __halves2half2(__float2half(acc[mi][ni][0] + bb0),
                                   __float2half(acc[mi][ni][1] + bb1));
            if (r1 < M)
                *(__half2*)(Ch + (size_t)r1 * N + col) =
                    __halves2half2(__float2half(acc[mi][ni][2] + bb0),
                                   __float2half(acc[mi][ni][3] + bb1));
        }
    }
}

// ---------------------------------------------------------------------------
// Fused GEMM2 + bias + residual + LayerNorm.
// Out = LN(A @ B^T + bias + resid), N=512 entirely within one CTA.
// BM=64, BN=512, BK=64, 512 threads (16 warps 4x4), warp tile 16x128.
// 2-stage double buffer; epilogue stages y in smem (stride 516), computes
// per-row mean/var via shfl + cross-warp smem partials, writes Out directly.
// ---------------------------------------------------------------------------
#define ROW2 144
#define S2_B (64 * ROW2)               // A: 0..9216, B after
#define STAGE2 (S2_B + 512 * ROW2)     // 82944
#define OFF_BIAS2 (2 * STAGE2)         // 165888
#define OFF_PART (OFF_BIAS2 + 2048)    // 167936
#define G2_SMEM (OFF_PART + 2048)      // 169984
#define YSTRIDE 516

__device__ __forceinline__ void load_tile2(
    uint32_t stage,
    const __half* __restrict__ Ah, const __half* __restrict__ Bh,
    int bm, int M, int kt, int tid)
{
    const int k0 = kt * 64;
    {   // A: 64 rows x 8 16B-chunks = 512 (one pass with 512 threads)
        int row = tid >> 3, c = tid & 7;
        uint32_t dof = row * ROW2 + c * 16;
        size_t ga = (size_t)(bm + row) * KDIM + k0 + c * 8;
        int p = ((bm + row) < M) ? 16 : 0;
        CP_ASYNC16(stage + dof, Ah + ga, p);
    }
#pragma unroll
    for (int i = 0; i < 8; i++) {     // B: 512 rows x 8 16B-chunks
        int q = i * 512 + tid;
        int row = q >> 3, c = q & 7;
        uint32_t dof = row * ROW2 + c * 16;
        size_t gb = (size_t)row * KDIM + k0 + c * 8;
        CP_ASYNC16(stage + S2_B + dof, Bh + gb, 16);
    }
}

__global__ void __launch_bounds__(512, 1) gemm2_ln(
    const __half* __restrict__ Ah, const __half* __restrict__ Bh,
    const float* __restrict__ bias, const float* __restrict__ resid,
    float* __restrict__ Out, int M)
{
    extern __shared__ char smem[];
    const uint32_t sb = smem_u32(smem);
    const int tid = threadIdx.x;
    const int w = tid >> 5, lane = tid & 31;
    const int wm = w & 3;                 // 4 warp-rows of 16
    const int wn = w >> 2;                // 4 warp-cols of 128
    const int bm = blockIdx.x << 6;       // BM=64

    float* bias_s = (float*)(smem + OFF_BIAS2);
    bias_s[tid] = bias[tid];              // 512 threads load 512 biases

    float acc[16][4];
#pragma unroll
    for (int j = 0; j < 16; j++)
#pragma unroll
        for (int e = 0; e < 4; e++) acc[j][e] = 0.f;

    const int lrow = lane & 15;
    const int lkb = (lane >> 4) << 4;
    const uint32_t a_lane_off = (wm * 16 + lrow) * ROW2 + lkb;
    const uint32_t b_lane_off = (wn * 128 + lrow) * ROW2 + lkb;

    const int T = KDIM / 64;              // 8
    load_tile2(sb, Ah, Bh, bm, M, 0, tid);
    CP_COMMIT();

    for (int kt = 0; kt < T; kt++) {
        CP_WAIT0();
        __syncthreads();

        if (kt + 1 < T) {
            load_tile2(sb + ((kt + 1) & 1) * STAGE2, Ah, Bh, bm, M, kt + 1, tid);
            CP_COMMIT();
        }

        const uint32_t stage = sb + (kt & 1) * STAGE2;
#pragma unroll
        for (int kc = 0; kc < 4; kc++) {
            const uint32_t kbo = kc * 32;
            uint32_t ah[4], bh[16][2];
            LDSM4(ah[0], ah[1], ah[2], ah[3], stage + a_lane_off + kbo);
#pragma unroll
            for (int nj = 0; nj < 8; nj++) {
                uint32_t bd = stage + S2_B + b_lane_off + nj * (16 * ROW2) + kbo;
                uint32_t h0, h1, h2r, h3;
                LDSM4(h0, h1, h2r, h3, bd);
                bh[nj * 2 + 0][0] = h0; bh[nj * 2 + 0][1] = h2r;
                bh[nj * 2 + 1][0] = h1; bh[nj * 2 + 1][1] = h3;
            }
#pragma unroll
            for (int nq = 0; nq < 16; nq++)
                mma16816(acc[nq], ah, bh[nq]);
        }
    }

    // ---- fused epilogue: bias + residual + LayerNorm ----
    __syncthreads();                       // all warps done with smem stages
    float* yv = (float*)smem;              // [64][YSTRIDE]
    float* part = (float*)(smem + OFF_PART);   // [4 wn][64 rows][2]
    const int g = lane >> 2, t = lane & 3;

    // pass 1: materialize y, per-(wn,row) partial sums
#pragma unroll
    for (int half = 0; half < 2; half++) {
        int rl = wm * 16 + half * 8 + g;
        int rg = bm + rl;
        float sum = 0.f, sq = 0.f;
#pragma unroll
        for (int ni = 0; ni < 16; ni++) {
            int col = wn * 128 + ni * 8 + t * 2;
            float v0 = acc[ni][half * 2 + 0] + bias_s[col];
            float v1 = acc[ni][half * 2 + 1] + bias_s[col + 1];
            if (rg < M) {
                float2 rr = *(const float2*)(resid + (size_t)rg * 512 + col);
                v0 += rr.x; v1 += rr.y;
            }
            yv[rl * YSTRIDE + col] = v0;
            yv[rl * YSTRIDE + col + 1] = v1;
            sum += v0 + v1;
            sq += v0 * v0 + v1 * v1;
        }
        sum += __shfl_xor_sync(0xffffffffu, sum, 1);
        sq  += __shfl_xor_sync(0xffffffffu, sq, 1);
        sum += __shfl_xor_sync(0xffffffffu, sum, 2);
        sq  += __shfl_xor_sync(0xffffffffu, sq, 2);
        if (t == 0) {
            part[(wn * 64 + rl) * 2 + 0] = sum;
            part[(wn * 64 + rl) * 2 + 1] = sq;
        }
    }
    __syncthreads();

    // pass 2: normalize + store
#pragma unroll
    for (int half = 0; half < 2; half++) {
        int rl = wm * 16 + half * 8 + g;
        int rg = bm + rl;
        if (rg >= M) continue;
        float sum = part[rl * 2]             + part[(64 + rl) * 2]
                  + part[(128 + rl) * 2]     + part[(192 + rl) * 2];
        float sq  = part[rl * 2 + 1]         + part[(64 + rl) * 2 + 1]
                  + part[(128 + rl) * 2 + 1] + part[(192 + rl) * 2 + 1];
        float mean = sum * (1.f / 512.f);
        float var = sq * (1.f / 512.f) - mean * mean;
        float rinv = rsqrtf(var + 1e-5f);
#pragma unroll
        for (int ni = 0; ni < 16; ni++) {
            int col = wn * 128 + ni * 8 + t * 2;
            float2 o;
            o.x = (yv[rl * YSTRIDE + col] - mean) * rinv;
            o.y = (yv[rl * YSTRIDE + col + 1] - mean) * rinv;
            *(float2*)(Out + (size_t)rg * 512 + col) = o;
        }
    }
}

// ---------------------------------------------------------------------------
// Elementwise fp32 -> fp16 convert
// ---------------------------------------------------------------------------
__global__ void cvt_kernel(const float* __restrict__ src,
                           __half* __restrict__ dst, int n4) {
    int i = blockIdx.x * blockDim.x + threadIdx.x;
    if (i >= n4) return;
    float4 v = ((const float4*)src)[i];
    __half2* dp = (__half2*)dst;
    dp[2 * i]     = __halves2half2(__float2half(v.x), __float2half(v.y));
    dp[2 * i + 1] = __halves2half2(__float2half(v.z), __float2half(v.w));
}

// Transpose to fp16: W (KxN row-major) -> hiT (NxK row-major)
__global__ void wsplit_kernel(const float* __restrict__ W,
                              __half* __restrict__ hiT, int K, int N) {
    __shared__ float t[32][33];
    const int n0 = blockIdx.x * 32, k0 = blockIdx.y * 32;
    const int tx = threadIdx.x, ty = threadIdx.y;
    for (int r = ty; r < 32; r += 8)
        t[r][tx] = W[(size_t)(k0 + r) * N + n0 + tx];
    __syncthreads();
    for (int r = ty; r < 32; r += 8) {
        float v = t[tx][r];
        hiT[(size_t)(n0 + r) * K + k0 + tx] = __float2half(v);
    }
}

// ---------------------------------------------------------------------------
// Attention (R12/R14 proven version): 2 heads per 128-thread block; qkv fp16
// in, fp32 math, fp16 out. 3x3 register-tiled scores; padded rows; reg P@V.
// ---------------------------------------------------------------------------
#define APAD 68
__global__ __launch_bounds__(128)
void attn_kernel(const __half* __restrict__ qkv, __half* __restrict__ oh) {
    const int blk = blockIdx.x;
    const int bn = blk >> 2;
    const int h  = ((blk & 3) << 1) + (threadIdx.x >> 6);
    const int sl = threadIdx.x >> 6;
    const int d  = threadIdx.x & 63;

    __shared__ float qs[2][18][APAD];
    __shared__ float ks[2][18][APAD];
    __shared__ float vs[2][17][APAD];
    __shared__ float S[2][17][20];

    const __half* base = qkv + (size_t)bn * 17 * 1536 + h * 64;
#pragma unroll
    for (int j = 0; j < 17; j++) {
        const __half* r = base + (size_t)j * 1536;
        qs[sl][j][d] = __half2float(r[d]);
        ks[sl][j][d] = __half2float(r[512 + d]);
        vs[sl][j][d] = __half2float(r[1024 + d]);
    }
    qs[sl][17][d] = 0.f;
    ks[sl][17][d] = 0.f;
    __syncthreads();

    if (d < 36) {
        const int i0 = (d / 6) * 3;
        const int j0 = (d % 6) * 3;
        float a[3][3];
#pragma unroll
        for (int r = 0; r < 3; r++)
#pragma unroll
            for (int s = 0; s < 3; s++) a[r][s] = 0.f;

#pragma unroll
        for (int c = 0; c < 8; c++) {
            float qv[3][8], kv[3][8];
#pragma unroll
            for (int r = 0; r < 3; r++) {
                *(float4*)&qv[r][0] = *(const float4*)&qs[sl][i0 + r][c * 8];
                *(float4*)&qv[r][4] = *(const float4*)&qs[sl][i0 + r][c * 8 + 4];
                *(float4*)&kv[r][0] = *(const float4*)&ks[sl][j0 + r][c * 8];
                *(float4*)&kv[r][4] = *(const float4*)&ks[sl][j0 + r][c * 8 + 4];
            }
#pragma unroll
            for (int r = 0; r < 3; r++)
#pragma unroll
                for (int s = 0; s < 3; s++)
#pragma unroll
                    for (int e = 0; e < 8; e++)
                        a[r][s] += qv[r][e] * kv[s][e];
        }
#pragma unroll
        for (int r = 0; r < 3; r++)
#pragma unroll
            for (int s = 0; s < 3; s++)
                if (i0 + r < 17 && j0 + s < 17)
                    S[sl][i0 + r][j0 + s] = a[r][s] * 0.125f;
    }
    __syncthreads();

    if (d < 17) {
        float mx = -1e30f;
#pragma unroll
        for (int j = 0; j < 17; j++) mx = fmaxf(mx, S[sl][d][j]);
        float sum = 0.f;
#pragma unroll
        for (int j = 0; j < 17; j++) {
            float e = expf(S[sl][d][j] - mx);
            S[sl][d][j] = e;
            sum += e;
        }
        float inv = 1.f / sum;
#pragma unroll
        for (int j = 0; j < 17; j++) S[sl][d][j] *= inv;
    }
    __syncthreads();

    if (d == 0) {
        const int trip[13][3] = {
            {0,1,2},{1,2,3},{0,4,5},{4,5,6},{0,7,8},{7,8,9},{8,9,10},
            {7,8,11},{8,11,12},{11,12,13},{7,8,14},{8,14,15},{14,15,16}};
#pragma unroll
        for (int tt = 0; tt < 13; tt++) {
            int jp = trip[tt][0], j = trip[tt][1], jc = trip[tt][2];
            float half = S[sl][j][jp] * 0.5f;
            S[sl][j][jc] += half;
            S[sl][jc][j] += half;
        }
    }
    __syncthreads();

    float v[17];
#pragma unroll
    for (int j = 0; j < 17; j++) v[j] = vs[sl][j][d];
#pragma unroll
    for (int i = 0; i < 17; i++) {
        const float4 s0 = *(const float4*)&S[sl][i][0];
        const float4 s1 = *(const float4*)&S[sl][i][4];
        const float4 s2 = *(const float4*)&S[sl][i][8];
        const float4 s3 = *(const float4*)&S[sl][i][12];
        const float s16 = S[sl][i][16];
        float o = s0.x * v[0] + s0.y * v[1] + s0.z * v[2] + s0.w * v[3]
                + s1.x * v[4] + s1.y * v[5] + s1.z * v[6] + s1.w * v[7]
                + s2.x * v[8] + s2.y * v[9] + s2.z * v[10] + s2.w * v[11]
                + s3.x * v[12] + s3.y * v[13] + s3.z * v[14] + s3.w * v[15]
                + s16 * v[16];
        oh[((size_t)(bn * 17 + i)) * 512 + h * 64 + d] = __float2half(o);
    }
}

// ---------------------------------------------------------------------------
extern "C" void kernel_launch(void* const* d_in, const int* in_sizes, int n_in,
                              void* d_out, int out_size) {
    const float* x     = (const float*)d_in[0];
    const float* Wqkv  = (const float*)d_in[1];
    const float* bqkv  = (const float*)d_in[2];
    const float* Wproj = (const float*)d_in[3];
    const float* bproj = (const float*)d_in[4];
    float* out = (float*)d_out;

    __half *qkvh, *xh, *ah, *w1h, *w2h;
    cudaGetSymbolAddress((void**)&qkvh, g_qkvh);
    cudaGetSymbolAddress((void**)&xh, g_xh);
    cudaGetSymbolAddress((void**)&ah, g_ah);
    cudaGetSymbolAddress((void**)&w1h, g_w1h);
    cudaGetSymbolAddress((void**)&w2h, g_w2h);

    cudaFuncSetAttribute(gemm_mma, cudaFuncAttributeMaxDynamicSharedMemorySize, GEMM_SMEM);
    cudaFuncSetAttribute(gemm2_ln, cudaFuncAttributeMaxDynamicSharedMemorySize, G2_SMEM);

    // 1) converts
    const int n4 = MROWS * CC / 4;
    cvt_kernel<<<(n4 + 255) / 256, 256>>>(x, xh, n4);
    wsplit_kernel<<<dim3(1536 / 32, 512 / 32), dim3(32, 8)>>>(Wqkv, w1h, 512, 1536);
    wsplit_kernel<<<dim3(512 / 32, 512 / 32), dim3(32, 8)>>>(Wproj, w2h, 512, 512);

    // 2) GEMM1: qkv = x @ Wqkv + bqkv (fp16 out)
    gemm_mma<<<dim3(1536 / 128, (MROWS + 127) / 128), 256, GEMM_SMEM>>>(
        xh, w1h, bqkv, qkvh, MROWS, 1536);

    // 3) attention (fp16 in/out)
    attn_kernel<<<BNF * 4, 128>>>(qkvh, ah);

    // 4) fused GEMM2 + bias + residual + LayerNorm -> out
    gemm2_ln<<<(MROWS + 63) / 64, 512, G2_SMEM>>>(ah, w2h, bproj, x, out, MROWS);
}

// round 17
// speedup vs baseline: 1.1953x; 1.0116x over previous
#include <cuda_runtime.h>
#include <cuda_fp16.h>
#include <math.h>
#include <stdint.h>

// Problem constants
#define BB 16
#define NN 243
#define JJ 17
#define CC 512
#define HH 8
#define MROWS (BB * NN * JJ)      // 66096
#define BNF   (BB * NN)           // 3888
#define KDIM  512

// Scratch (device globals: allocation-free per harness rules)
__device__ __half g_qkvh[(size_t)MROWS * 1536];
__device__ __half g_yh[(size_t)MROWS * CC];
__device__ __half g_xh[(size_t)MROWS * CC];
__device__ __half g_ah[(size_t)MROWS * CC];
__device__ __half g_w1h[1536 * 512];   // Wqkv^T fp16, [N][K]
__device__ __half g_w2h[512 * 512];    // Wproj^T fp16

// ---------------------------------------------------------------------------
// PTX helpers
// ---------------------------------------------------------------------------
__device__ __forceinline__ uint32_t smem_u32(const void* p) {
    uint32_t a;
    asm("{ .reg .u64 t; cvta.to.shared.u64 t, %1; cvt.u32.u64 %0, t; }"
        : "=r"(a) : "l"(p));
    return a;
}

#define CP_ASYNC16(dst, src, sz) \
    asm volatile("cp.async.cg.shared.global [%0], [%1], 16, %2;\n" \
                 :: "r"((uint32_t)(dst)), "l"(src), "r"(sz))
#define CP_COMMIT() asm volatile("cp.async.commit_group;\n" ::: "memory")
#define CP_WAIT0()  asm volatile("cp.async.wait_group 0;\n" ::: "memory")

#define LDSM4(r0, r1, r2, r3, a) \
    asm volatile("ldmatrix.sync.aligned.m8n8.x4.shared.b16 {%0,%1,%2,%3}, [%4];" \
                 : "=r"(r0), "=r"(r1), "=r"(r2), "=r"(r3) : "r"(a))

__device__ __forceinline__ void mma16816(float* c, const uint32_t* a, const uint32_t* b) {
    asm volatile(
        "mma.sync.aligned.m16n8k16.row.col.f32.f16.f16.f32 "
        "{%0,%1,%2,%3}, {%4,%5,%6,%7}, {%8,%9}, {%0,%1,%2,%3};\n"
        : "+f"(c[0]), "+f"(c[1]), "+f"(c[2]), "+f"(c[3])
        : "r"(a[0]), "r"(a[1]), "r"(a[2]), "r"(a[3]), "r"(b[0]), "r"(b[1]));
}

// ---------------------------------------------------------------------------
// fp16 HMMA GEMM (R14 proven config): C = A @ B^T + bias (+resid), fp32 acc.
// Output fp16 (Ch) if Ch != null else fp32 (Cf); resid supported in both.
// BM=128, BN=128, BK=64, 256 threads (8 warps 2x4), warp 64x32.
// 2 CTAs/SM; 2-stage double buffer; 144B-padded rows (conflict-free ldmatrix).
// ---------------------------------------------------------------------------
#define ROWB 144
#define ST_A 0
#define ST_B (128 * ROWB)              // 18432
#define STAGE_BYTES (ST_B + 128 * ROWB)    // 36864
#define GEMM_SMEM (2 * STAGE_BYTES)        // 73728

__device__ __forceinline__ void load_tile(
    uint32_t stage,
    const __half* __restrict__ Ah, const __half* __restrict__ Bh,
    int bm, int bn, int M, int kt, int tid)
{
    const int k0 = kt * 64;
#pragma unroll
    for (int i = 0; i < 4; i++) {     // A: 128 rows x 8 16B-chunks
        int q = i * 256 + tid;
        int row = q >> 3, c = q & 7;
        uint32_t dof = row * ROWB + c * 16;
        size_t ga = (size_t)(bm + row) * KDIM + k0 + c * 8;
        int p = ((bm + row) < M) ? 16 : 0;
        CP_ASYNC16(stage + ST_A + dof, Ah + ga, p);
    }
#pragma unroll
    for (int i = 0; i < 4; i++) {     // B: 128 rows x 8 16B-chunks
        int q = i * 256 + tid;
        int row = q >> 3, c = q & 7;
        uint32_t dof = row * ROWB + c * 16;
        size_t gb = (size_t)(bn + row) * KDIM + k0 + c * 8;
        CP_ASYNC16(stage + ST_B + dof, Bh + gb, 16);
    }
}

__global__ void __launch_bounds__(256, 2) gemm_mma(
    const __half* __restrict__ Ah, const __half* __restrict__ Bh,
    const float* __restrict__ bias, const float* __restrict__ resid,
    float* __restrict__ Cf, __half* __restrict__ Ch, int M, int N)
{
    extern __shared__ char smem[];
    const uint32_t sb = smem_u32(smem);
    const int tid = threadIdx.x;
    const int w = tid >> 5, lane = tid & 31;
    const int wm = w & 1;
    const int wn = w >> 1;
    const int bn = blockIdx.x << 7;
    const int bm = blockIdx.y << 7;

    float acc[4][4][4];
#pragma unroll
    for (int i = 0; i < 4; i++)
#pragma unroll
        for (int j = 0; j < 4; j++)
#pragma unroll
            for (int e = 0; e < 4; e++) acc[i][j][e] = 0.f;

    const int lrow = lane & 15;
    const int lkb = (lane >> 4) << 4;
    const uint32_t a_lane_off = (wm * 64 + lrow) * ROWB + lkb;
    const uint32_t b_lane_off = (wn * 32 + lrow) * ROWB + lkb;

    const int T = KDIM / 64;              // 8
    load_tile(sb, Ah, Bh, bm, bn, M, 0, tid);
    CP_COMMIT();

    for (int kt = 0; kt < T; kt++) {
        CP_WAIT0();
        __syncthreads();

        if (kt + 1 < T) {
            load_tile(sb + ((kt + 1) & 1) * STAGE_BYTES, Ah, Bh, bm, bn, M, kt + 1, tid);
            CP_COMMIT();
        }

        const uint32_t stage = sb + (kt & 1) * STAGE_BYTES;
#pragma unroll
        for (int kc = 0; kc < 4; kc++) {
            const uint32_t kbo = kc * 32;
            uint32_t ah[4][4], bh[4][2];
#pragma unroll
            for (int mi = 0; mi < 4; mi++) {
                uint32_t ad = stage + a_lane_off + mi * (16 * ROWB) + kbo;
                LDSM4(ah[mi][0], ah[mi][1], ah[mi][2], ah[mi][3], ad + ST_A);
            }
#pragma unroll
            for (int nj = 0; nj < 2; nj++) {
                uint32_t bd = stage + b_lane_off + nj * (16 * ROWB) + kbo;
                uint32_t h0, h1, h2r, h3;
                LDSM4(h0, h1, h2r, h3, bd + ST_B);
                bh[nj * 2 + 0][0] = h0; bh[nj * 2 + 0][1] = h2r;
                bh[nj * 2 + 1][0] = h1; bh[nj * 2 + 1][1] = h3;
            }
#pragma unroll
            for (int mi = 0; mi < 4; mi++)
#pragma unroll
                for (int nq = 0; nq < 4; nq++)
                    mma16816(acc[mi][nq], ah[mi], bh[nq]);
        }
    }

    const int g = lane >> 2, t = lane & 3;
#pragma unroll
    for (int mi = 0; mi < 4; mi++) {
#pragma unroll
        for (int ni = 0; ni < 4; ni++) {
            int col = bn + wn * 32 + ni * 8 + t * 2;
            float bb0 = bias[col], bb1 = bias[col + 1];
            int r0 = bm + wm * 64 + mi * 16 + g;
            int r1 = r0 + 8;
#pragma unroll
            for (int rr2 = 0; rr2 < 2; rr2++) {
                int r = rr2 ? r1 : r0;
                if (r >= M) continue;
                float v0 = acc[mi][ni][rr2 * 2 + 0] + bb0;
                float v1 = acc[mi][ni][rr2 * 2 + 1] + bb1;
                if (resid) {
                    const float2 rv = *(const float2*)(resid + (size_t)r * N + col);
                    v0 += rv.x; v1 += rv.y;
                }
                if (Ch)
                    *(__half2*)(Ch + (size_t)r * N + col) =
                        __halves2half2(__float2half(v0), __float2half(v1));
                else
                    *(float2*)(Cf + (size_t)r * N + col) = make_float2(v0, v1);
            }
        }
    }
}

// ---------------------------------------------------------------------------
// Elementwise fp32 -> fp16 convert
// ---------------------------------------------------------------------------
__global__ void cvt_kernel(const float* __restrict__ src,
                           __half* __restrict__ dst, int n4) {
    int i = blockIdx.x * blockDim.x + threadIdx.x;
    if (i >= n4) return;
    float4 v = ((const float4*)src)[i];
    __half2* dp = (__half2*)dst;
    dp[2 * i]     = __halves2half2(__float2half(v.x), __float2half(v.y));
    dp[2 * i + 1] = __halves2half2(__float2half(v.z), __float2half(v.w));
}

// Transpose to fp16: W (KxN row-major) -> hiT (NxK row-major)
__global__ void wsplit_kernel(const float* __restrict__ W,
                              __half* __restrict__ hiT, int K, int N) {
    __shared__ float t[32][33];
    const int n0 = blockIdx.x * 32, k0 = blockIdx.y * 32;
    const int tx = threadIdx.x, ty = threadIdx.y;
    for (int r = ty; r < 32; r += 8)
        t[r][tx] = W[(size_t)(k0 + r) * N + n0 + tx];
    __syncthreads();
    for (int r = ty; r < 32; r += 8) {
        float v = t[tx][r];
        hiT[(size_t)(n0 + r) * K + k0 + tx] = __float2half(v);
    }
}

// ---------------------------------------------------------------------------
// Attention: 2 heads per 128-thread block; qkv fp16 in, fp32 math, fp16 out.
// Scores via 2x3 register tiles over 9x6 grid (54/64 threads active per
// slice, both warps ~85% populated -> critical-warp FMA count -33%).
// ---------------------------------------------------------------------------
#define APAD 68
__global__ __launch_bounds__(128)
void attn_kernel(const __half* __restrict__ qkv, __half* __restrict__ oh) {
    const int blk = blockIdx.x;
    const int bn = blk >> 2;
    const int h  = ((blk & 3) << 1) + (threadIdx.x >> 6);
    const int sl = threadIdx.x >> 6;
    const int d  = threadIdx.x & 63;

    __shared__ float qs[2][18][APAD];
    __shared__ float ks[2][18][APAD];
    __shared__ float vs[2][17][APAD];
    __shared__ float S[2][17][20];

    const __half* base = qkv + (size_t)bn * 17 * 1536 + h * 64;
#pragma unroll
    for (int j = 0; j < 17; j++) {
        const __half* r = base + (size_t)j * 1536;
        qs[sl][j][d] = __half2float(r[d]);
        ks[sl][j][d] = __half2float(r[512 + d]);
        vs[sl][j][d] = __half2float(r[1024 + d]);
    }
    qs[sl][17][d] = 0.f;
    ks[sl][17][d] = 0.f;
    __syncthreads();

    // Scores: 9x6 grid of 2x3 tiles over padded 18x18 domain; threads 0..53
    if (d < 54) {
        const int i0 = (d / 6) * 2;
        const int j0 = (d % 6) * 3;
        float a[2][3];
#pragma unroll
        for (int r = 0; r < 2; r++)
#pragma unroll
            for (int s = 0; s < 3; s++) a[r][s] = 0.f;

#pragma unroll
        for (int c = 0; c < 8; c++) {
            float qv[2][8], kv[3][8];
#pragma unroll
            for (int r = 0; r < 2; r++) {
                *(float4*)&qv[r][0] = *(const float4*)&qs[sl][i0 + r][c * 8];
                *(float4*)&qv[r][4] = *(const float4*)&qs[sl][i0 + r][c * 8 + 4];
            }
#pragma unroll
            for (int s = 0; s < 3; s++) {
                *(float4*)&kv[s][0] = *(const float4*)&ks[sl][j0 + s][c * 8];
                *(float4*)&kv[s][4] = *(const float4*)&ks[sl][j0 + s][c * 8 + 4];
            }
#pragma unroll
            for (int r = 0; r < 2; r++)
#pragma unroll
                for (int s = 0; s < 3; s++)
#pragma unroll
                    for (int e = 0; e < 8; e++)
                        a[r][s] += qv[r][e] * kv[s][e];
        }
#pragma unroll
        for (int r = 0; r < 2; r++)
#pragma unroll
            for (int s = 0; s < 3; s++)
                if (i0 + r < 17 && j0 + s < 17)
                    S[sl][i0 + r][j0 + s] = a[r][s] * 0.125f;
    }
    __syncthreads();

    if (d < 17) {
        float mx = -1e30f;
#pragma unroll
        for (int j = 0; j < 17; j++) mx = fmaxf(mx, S[sl][d][j]);
        float sum = 0.f;
#pragma unroll
        for (int j = 0; j < 17; j++) {
            float e = expf(S[sl][d][j] - mx);
            S[sl][d][j] = e;
            sum += e;
        }
        float inv = 1.f / sum;
#pragma unroll
        for (int j = 0; j < 17; j++) S[sl][d][j] *= inv;
    }
    __syncthreads();

    if (d == 0) {
        const int trip[13][3] = {
            {0,1,2},{1,2,3},{0,4,5},{4,5,6},{0,7,8},{7,8,9},{8,9,10},
            {7,8,11},{8,11,12},{11,12,13},{7,8,14},{8,14,15},{14,15,16}};
#pragma unroll
        for (int tt = 0; tt < 13; tt++) {
            int jp = trip[tt][0], j = trip[tt][1], jc = trip[tt][2];
            float half = S[sl][j][jp] * 0.5f;
            S[sl][j][jc] += half;
            S[sl][jc][j] += half;
        }
    }
    __syncthreads();

    float v[17];
#pragma unroll
    for (int j = 0; j < 17; j++) v[j] = vs[sl][j][d];
#pragma unroll
    for (int i = 0; i < 17; i++) {
        const float4 s0 = *(const float4*)&S[sl][i][0];
        const float4 s1 = *(const float4*)&S[sl][i][4];
        const float4 s2 = *(const float4*)&S[sl][i][8];
        const float4 s3 = *(const float4*)&S[sl][i][12];
        const float s16 = S[sl][i][16];
        float o = s0.x * v[0] + s0.y * v[1] + s0.z * v[2] + s0.w * v[3]
                + s1.x * v[4] + s1.y * v[5] + s1.z * v[6] + s1.w * v[7]
                + s2.x * v[8] + s2.y * v[9] + s2.z * v[10] + s2.w * v[11]
                + s3.x * v[12] + s3.y * v[13] + s3.z * v[14] + s3.w * v[15]
                + s16 * v[16];
        oh[((size_t)(bn * 17 + i)) * 512 + h * 64 + d] = __float2half(o);
    }
}

// ---------------------------------------------------------------------------
// LayerNorm (no affine) over last dim 512; fp16 input, fp32 output.
// ---------------------------------------------------------------------------
__global__ __launch_bounds__(128)
void ln_kernel(const __half* __restrict__ Y, float* __restrict__ O) {
    const int row = blockIdx.x;
    const int t = threadIdx.x;
    const uint2 raw = *(const uint2*)(Y + (size_t)row * 512 + t * 4);
    const __half2* hp = (const __half2*)&raw;
    float2 f0 = __half22float2(hp[0]);
    float2 f1 = __half22float2(hp[1]);
    float4 v = make_float4(f0.x, f0.y, f1.x, f1.y);

    float s = v.x + v.y + v.z + v.w;
    float q = v.x * v.x + v.y * v.y + v.z * v.z + v.w * v.w;
#pragma unroll
    for (int o = 16; o > 0; o >>= 1) {
        s += __shfl_xor_sync(0xffffffffu, s, o);
        q += __shfl_xor_sync(0xffffffffu, q, o);
    }
    __shared__ float ss[4], sq[4];
    int w = t >> 5;
    if ((t & 31) == 0) { ss[w] = s; sq[w] = q; }
    __syncthreads();
    s = ss[0] + ss[1] + ss[2] + ss[3];
    q = sq[0] + sq[1] + sq[2] + sq[3];

    const float inv512 = 1.f / 512.f;
    float mean = s * inv512;
    float var = q * inv512 - mean * mean;
    float r = rsqrtf(var + 1e-5f);

    float4 o4;
    o4.x = (v.x - mean) * r;
    o4.y = (v.y - mean) * r;
    o4.z = (v.z - mean) * r;
    o4.w = (v.w - mean) * r;
    *(float4*)(O + (size_t)row * 512 + t * 4) = o4;
}

// ---------------------------------------------------------------------------
extern "C" void kernel_launch(void* const* d_in, const int* in_sizes, int n_in,
                              void* d_out, int out_size) {
    const float* x     = (const float*)d_in[0];
    const float* Wqkv  = (const float*)d_in[1];
    const float* bqkv  = (const float*)d_in[2];
    const float* Wproj = (const float*)d_in[3];
    const float* bproj = (const float*)d_in[4];
    float* out = (float*)d_out;

    __half *qkvh, *yh, *xh, *ah, *w1h, *w2h;
    cudaGetSymbolAddress((void**)&qkvh, g_qkvh);
    cudaGetSymbolAddress((void**)&yh, g_yh);
    cudaGetSymbolAddress((void**)&xh, g_xh);
    cudaGetSymbolAddress((void**)&ah, g_ah);
    cudaGetSymbolAddress((void**)&w1h, g_w1h);
    cudaGetSymbolAddress((void**)&w2h, g_w2h);

    cudaFuncSetAttribute(gemm_mma, cudaFuncAttributeMaxDynamicSharedMemorySize, GEMM_SMEM);

    // 1) converts
    const int n4 = MROWS * CC / 4;
    cvt_kernel<<<(n4 + 255) / 256, 256>>>(x, xh, n4);
    wsplit_kernel<<<dim3(1536 / 32, 512 / 32), dim3(32, 8)>>>(Wqkv, w1h, 512, 1536);
    wsplit_kernel<<<dim3(512 / 32, 512 / 32), dim3(32, 8)>>>(Wproj, w2h, 512, 512);

    // 2) GEMM1: qkv = x @ Wqkv + bqkv (fp16 out)
    gemm_mma<<<dim3(1536 / 128, (MROWS + 127) / 128), 256, GEMM_SMEM>>>(
        xh, w1h, bqkv, nullptr, nullptr, qkvh, MROWS, 1536);

    // 3) attention (fp16 in/out)
    attn_kernel<<<BNF * 4, 128>>>(qkvh, ah);

    // 4) GEMM2: yh = att @ Wproj + bproj + x (fp16 out + resid)
    gemm_mma<<<dim3(512 / 128, (MROWS + 127) / 128), 256, GEMM_SMEM>>>(
        ah, w2h, bproj, x, nullptr, yh, MROWS, 512);

    // 5) LayerNorm (fp16 in, fp32 out)
    ln_kernel<<<MROWS, 128>>>(yh, out);
}